// round 1
// baseline (speedup 1.0000x reference)
#include <cuda_runtime.h>
#include <cuda_bf16.h>
#include <float.h>
#include <math.h>

// Problem constants
#define T_TOK 8192
#define D_DIM 7168
#define E_EXP 256
#define N_GROUPS 8
#define EXPERTS_PER_GROUP 32   // E/N_GROUPS
#define TOPK_GROUPS 4
#define TOP_K 8

// GEMM tiling
#define BM 64
#define BN 64
#define BK 16

// scratch: sigmoid scores [T, E] (8 MB)
__device__ float g_scores[(size_t)T_TOK * E_EXP];

// ---------------------------------------------------------------------------
// GEMM: scores = sigmoid(x @ W), fp32 accumulate (matches jnp.float32).
// Block = 64x64 tile, 256 threads, each thread 4x4 micro-tile.
// ---------------------------------------------------------------------------
__global__ __launch_bounds__(256) void gemm_sigmoid_kernel(
    const float* __restrict__ A,   // [T, D]
    const float* __restrict__ B)   // [D, E]
{
    __shared__ float As[BK][BM + 4];   // +4 pad: kills STS bank conflicts, keeps 16B align
    __shared__ float Bs[BK][BN];

    const int tid = threadIdx.x;
    const int m0  = blockIdx.y * BM;
    const int n0  = blockIdx.x * BN;

    // global-load mapping
    const int la_row = tid >> 2;          // 0..63  (A row within tile)
    const int la_col = (tid & 3) * 4;     // 0,4,8,12 (k offset)
    const int lb_row = tid >> 4;          // 0..15  (k row)
    const int lb_col = (tid & 15) * 4;    // 0..60  (n offset)

    // compute mapping: 16 row-groups x 16 col-groups
    const int tm = (tid >> 4) * 4;        // 0..60
    const int tn = (tid & 15) * 4;        // 0..60

    float acc[4][4];
#pragma unroll
    for (int i = 0; i < 4; i++)
#pragma unroll
        for (int j = 0; j < 4; j++) acc[i][j] = 0.0f;

    const float* Aptr = A + (size_t)(m0 + la_row) * D_DIM + la_col;
    const float* Bptr = B + (size_t)lb_row * E_EXP + n0 + lb_col;

    for (int k0 = 0; k0 < D_DIM; k0 += BK) {
        float4 av = *(const float4*)(Aptr + k0);
        float4 bv = *(const float4*)(Bptr + (size_t)k0 * E_EXP);

        As[la_col + 0][la_row] = av.x;
        As[la_col + 1][la_row] = av.y;
        As[la_col + 2][la_row] = av.z;
        As[la_col + 3][la_row] = av.w;
        *(float4*)&Bs[lb_row][lb_col] = bv;
        __syncthreads();

#pragma unroll
        for (int k = 0; k < BK; k++) {
            float4 a = *(const float4*)&As[k][tm];
            float4 b = *(const float4*)&Bs[k][tn];
            acc[0][0] += a.x * b.x; acc[0][1] += a.x * b.y; acc[0][2] += a.x * b.z; acc[0][3] += a.x * b.w;
            acc[1][0] += a.y * b.x; acc[1][1] += a.y * b.y; acc[1][2] += a.y * b.z; acc[1][3] += a.y * b.w;
            acc[2][0] += a.z * b.x; acc[2][1] += a.z * b.y; acc[2][2] += a.z * b.z; acc[2][3] += a.z * b.w;
            acc[3][0] += a.w * b.x; acc[3][1] += a.w * b.y; acc[3][2] += a.w * b.z; acc[3][3] += a.w * b.w;
        }
        __syncthreads();
    }

#pragma unroll
    for (int i = 0; i < 4; i++) {
        float* crow = g_scores + (size_t)(m0 + tm + i) * E_EXP + n0 + tn;
#pragma unroll
        for (int j = 0; j < 4; j++) {
            float v = acc[i][j];
            crow[j] = 1.0f / (1.0f + expf(-v));   // sigmoid
        }
    }
}

// ---------------------------------------------------------------------------
// Routing: one block (256 threads) per token; warp == group (32 experts).
// Replicates jax.lax.top_k tie semantics: equal values -> lowest index first.
// ---------------------------------------------------------------------------
__global__ __launch_bounds__(256) void route_kernel(
    const float* __restrict__ bias,   // [E]
    float* __restrict__ out,          // weights at [0, T*8), indices-as-float at [T*8, 2*T*8)
    int write_indices)
{
    const int t    = blockIdx.x;
    const int e    = threadIdx.x;       // expert id == thread id
    const int lane = e & 31;
    const int warp = e >> 5;            // == group id

    __shared__ float gsc[N_GROUPS];
    __shared__ unsigned keepmask;
    __shared__ float wv[N_GROUPS];      // per-warp current best value
    __shared__ int   wi[N_GROUPS];      // per-warp current best (global) expert idx
    __shared__ int   sel_idx[TOP_K];
    __shared__ int   sel_warp;
    __shared__ float selw[TOP_K];

    const float score = g_scores[(size_t)t * E_EXP + e];   // sigmoid score
    const float s     = score + bias[e];                   // biased, for selection only

    // ---- group score = top1 + top2 within warp ----
    {
        float v = s; int i = lane;
#pragma unroll
        for (int off = 16; off; off >>= 1) {
            float ov = __shfl_xor_sync(0xffffffffu, v, off);
            int   oi = __shfl_xor_sync(0xffffffffu, i, off);
            if (ov > v || (ov == v && oi < i)) { v = ov; i = oi; }
        }
        float m1 = v;               // all lanes agree
        float v2 = (lane == i) ? -FLT_MAX : s;
#pragma unroll
        for (int off = 16; off; off >>= 1) {
            float ov = __shfl_xor_sync(0xffffffffu, v2, off);
            v2 = fmaxf(v2, ov);
        }
        if (lane == 0) gsc[warp] = m1 + v2;
    }
    __syncthreads();

    // ---- pick top-4 groups (serial on thread 0; ties -> lowest group) ----
    if (e == 0) {
        unsigned m = 0;
#pragma unroll
        for (int it = 0; it < TOPK_GROUPS; it++) {
            int best = -1; float bv = -FLT_MAX;
#pragma unroll
            for (int g = 0; g < N_GROUPS; g++) {
                if (!((m >> g) & 1u) && gsc[g] > bv) { bv = gsc[g]; best = g; }
            }
            m |= (1u << best);
        }
        keepmask = m;
    }
    __syncthreads();

    // masked score: exactly 0.0f for dropped groups (reference semantics!)
    float cur = ((keepmask >> warp) & 1u) ? s : 0.0f;

    // warp argmax of `cur` (global expert index, lowest-index tiebreak)
    auto warp_best = [&](float v) {
        int i = e;
#pragma unroll
        for (int off = 16; off; off >>= 1) {
            float ov = __shfl_xor_sync(0xffffffffu, v, off);
            int   oi = __shfl_xor_sync(0xffffffffu, i, off);
            if (ov > v || (ov == v && oi < i)) { v = ov; i = oi; }
        }
        if (lane == 0) { wv[warp] = v; wi[warp] = i; }
    };

    warp_best(cur);
    __syncthreads();

    // ---- iterative top-8 across the 8 warp candidates ----
    for (int k = 0; k < TOP_K; k++) {
        if (e == 0) {
            int b = 0;
#pragma unroll
            for (int g = 1; g < N_GROUPS; g++) {
                if (wv[g] > wv[b] || (wv[g] == wv[b] && wi[g] < wi[b])) b = g;
            }
            sel_idx[k] = wi[b];
            sel_warp   = b;
        }
        __syncthreads();
        int sw = sel_warp;
        if (warp == sw) {
            if (e == sel_idx[k]) cur = -FLT_MAX;
            warp_best(cur);
        }
        __syncthreads();
    }

    // ---- gather sigmoid weights, normalize, scale, write ----
    if (e < TOP_K) selw[e] = g_scores[(size_t)t * E_EXP + sel_idx[e]];
    __syncthreads();
    if (e == 0) {
        float sum = 0.0f;
#pragma unroll
        for (int k = 0; k < TOP_K; k++) sum += selw[k];
        float scale = 2.5f / (sum + 1e-20f);
#pragma unroll
        for (int k = 0; k < TOP_K; k++) {
            out[(size_t)t * TOP_K + k] = selw[k] * scale;
            if (write_indices)
                out[(size_t)T_TOK * TOP_K + (size_t)t * TOP_K + k] = (float)sel_idx[k];
        }
    }
}

// ---------------------------------------------------------------------------
extern "C" void kernel_launch(void* const* d_in, const int* in_sizes, int n_in,
                              void* d_out, int out_size)
{
    const float* x    = (const float*)d_in[0];   // [T, D]
    const float* W    = (const float*)d_in[1];   // [D, E]
    const float* bias = (const float*)d_in[2];   // [E]
    float* out = (float*)d_out;

    dim3 gemm_grid(E_EXP / BN, T_TOK / BM);      // (4, 128)
    gemm_sigmoid_kernel<<<gemm_grid, 256>>>(x, W);

    int write_indices = (out_size >= 2 * T_TOK * TOP_K) ? 1 : 0;
    route_kernel<<<T_TOK, 256>>>(bias, out, write_indices);
}

// round 5
// speedup vs baseline: 1.1079x; 1.1079x over previous
#include <cuda_runtime.h>
#include <cuda_fp16.h>
#include <float.h>
#include <math.h>
#include <stdint.h>

// ---------------- problem constants ----------------
#define T_TOK 8192
#define D_DIM 7168
#define E_EXP 256
#define N_GROUPS 8
#define TOPK_GROUPS 4
#define TOP_K 8

// ---------------- GEMM tiling ----------------
#define BM 128
#define BN 64
#define BK 32
#define NCHUNK (D_DIM / BK)      // 224

#define SA_STR 36                // halves per A smem row
#define SB_STR 40                // halves per B smem row
#define A_HALVES (2 * 3 * 128 * SA_STR)   // stages*pieces*rows*stride = 27648
#define B_HALVES (2 * 3 * 64 * SB_STR)    // 15360
#define SMEM_BYTES ((A_HALVES + B_HALVES) * 2)   // 86016

// piece scales: x = xh + xm*2^-11 + xl*2^-22 (pieces stored pre-scaled into fp16-normal range)
#define SC_UP1   2048.0f           // 2^11
#define SC_DN1   4.8828125e-4f     // 2^-11
#define SC_UP2   4194304.0f        // 2^22

// ---------------- device scratch ----------------
__device__ float g_scores[(size_t)T_TOK * E_EXP];     // sigmoid scores [T][E]
__device__ __half g_Bh[(size_t)E_EXP * D_DIM];        // W^T piece hi   [E][D]
__device__ __half g_Bm[(size_t)E_EXP * D_DIM];        // W^T piece mid (x 2^11)
__device__ __half g_Bl[(size_t)E_EXP * D_DIM];        // W^T piece lo  (x 2^22)

// ---------------- helpers ----------------
__device__ __forceinline__ void mma16816(float* c, const uint32_t* a, const uint32_t* b) {
    asm volatile(
        "mma.sync.aligned.m16n8k16.row.col.f32.f16.f16.f32 "
        "{%0,%1,%2,%3}, {%4,%5,%6,%7}, {%8,%9}, {%0,%1,%2,%3};"
        : "+f"(c[0]), "+f"(c[1]), "+f"(c[2]), "+f"(c[3])
        : "r"(a[0]), "r"(a[1]), "r"(a[2]), "r"(a[3]), "r"(b[0]), "r"(b[1]));
}

// 3-way split of two floats -> three packed fp16 pairs (elem0 in low 16 bits)
__device__ __forceinline__ void split3_2(float fx, float fy,
                                         uint32_t& h, uint32_t& m, uint32_t& l) {
    __half hx = __float2half_rn(fx), hy = __float2half_rn(fy);
    float rx = fx - __half2float(hx), ry = fy - __half2float(hy);
    __half mx = __float2half_rn(rx * SC_UP1), my = __float2half_rn(ry * SC_UP1);
    float sx = rx - __half2float(mx) * SC_DN1, sy = ry - __half2float(my) * SC_DN1;
    __half lx = __float2half_rn(sx * SC_UP2), ly = __float2half_rn(sy * SC_UP2);
    h = ((uint32_t)__half_as_ushort(hy) << 16) | (uint32_t)__half_as_ushort(hx);
    m = ((uint32_t)__half_as_ushort(my) << 16) | (uint32_t)__half_as_ushort(mx);
    l = ((uint32_t)__half_as_ushort(ly) << 16) | (uint32_t)__half_as_ushort(lx);
}

// ---------------------------------------------------------------------------
// W split + transpose: W[k][e] f32 -> g_Bh/g_Bm/g_Bl [e][k]
// ---------------------------------------------------------------------------
__global__ __launch_bounds__(256) void wsplit_kernel(const float* __restrict__ W) {
    __shared__ float tile[32][33];
    const int k0 = blockIdx.x * 32, e0 = blockIdx.y * 32;
    const int tx = threadIdx.x, ty = threadIdx.y;   // 32 x 8
#pragma unroll
    for (int i = 0; i < 4; i++)
        tile[ty + 8 * i][tx] = W[(size_t)(k0 + ty + 8 * i) * E_EXP + e0 + tx];
    __syncthreads();
#pragma unroll
    for (int i = 0; i < 4; i++) {
        const int e = e0 + ty + 8 * i;
        const int k = k0 + tx;
        float f = tile[tx][ty + 8 * i];
        __half h = __float2half_rn(f);
        float r1 = f - __half2float(h);
        __half m = __float2half_rn(r1 * SC_UP1);
        float r2 = r1 - __half2float(m) * SC_DN1;
        __half l = __float2half_rn(r2 * SC_UP2);
        size_t o = (size_t)e * D_DIM + k;
        g_Bh[o] = h;
        g_Bm[o] = m;
        g_Bl[o] = l;
    }
}

// ---------------------------------------------------------------------------
// GEMM: scores = sigmoid(x @ W) via fp16x3-split mma.sync (6 terms, fp32-exact).
// Grid (4, 64) = 256 CTAs. CTA tile 128x64, 8 warps in 4(M)x2(N), warp tile 32x32.
// ---------------------------------------------------------------------------
__global__ __launch_bounds__(256, 1) void gemm_hmma3_kernel(const float* __restrict__ x) {
    extern __shared__ __half sm[];
#define AS_IDX(st, sp, r, k) ((((st) * 3 + (sp)) * 128 + (r)) * SA_STR + (k))
#define BS_IDX(st, sp, n, k) (A_HALVES + (((st) * 3 + (sp)) * 64 + (n)) * SB_STR + (k))

    const int tid = threadIdx.x;
    const int lane = tid & 31, wid = tid >> 5;
    const int m0 = blockIdx.y * BM;
    const int n0 = blockIdx.x * BN;
    const int wm = (wid & 3) * 32;     // warp M offset (4 warps down M)
    const int wn = (wid >> 2) * 32;    // warp N offset (2 warps across N)
    const int g = lane >> 2;           // group row
    const int t = lane & 3;            // thread-in-group

    float acc0[2][4][4], acc1[2][4][4], acc2[2][4][4];
#pragma unroll
    for (int i = 0; i < 2; i++)
#pragma unroll
        for (int j = 0; j < 4; j++)
#pragma unroll
            for (int q = 0; q < 4; q++) {
                acc0[i][j][q] = 0.0f; acc1[i][j][q] = 0.0f; acc2[i][j][q] = 0.0f;
            }

    // ---- global load mappings ----
    // A: row = tid>>1 (0..127), 16 floats at koff = (tid&1)*16
    const int arow = tid >> 1;
    const int akoff = (tid & 1) * 16;
    const float* Ap = x + (size_t)(m0 + arow) * D_DIM + akoff;
    // B: row = tid>>2 (0..63), 8 halves (1 uint4) at bu = (tid&3)*8
    const int brow = tid >> 2;
    const int bu = (tid & 3) * 8;
    const __half* Bph = g_Bh + (size_t)(n0 + brow) * D_DIM + bu;
    const __half* Bpm = g_Bm + (size_t)(n0 + brow) * D_DIM + bu;
    const __half* Bpl = g_Bl + (size_t)(n0 + brow) * D_DIM + bu;

    // ---- prologue: chunk 0 -> stage 0 ----
    {
        const float4* ap4 = (const float4*)Ap;
#pragma unroll
        for (int j = 0; j < 4; j++) {
            float4 v = ap4[j];
            uint32_t h0, m0_, l0, h1, m1_, l1;
            split3_2(v.x, v.y, h0, m0_, l0);
            split3_2(v.z, v.w, h1, m1_, l1);
            *(uint2*)&sm[AS_IDX(0, 0, arow, akoff + 4 * j)] = make_uint2(h0, h1);
            *(uint2*)&sm[AS_IDX(0, 1, arow, akoff + 4 * j)] = make_uint2(m0_, m1_);
            *(uint2*)&sm[AS_IDX(0, 2, arow, akoff + 4 * j)] = make_uint2(l0, l1);
        }
        *(uint4*)&sm[BS_IDX(0, 0, brow, bu)] = *(const uint4*)Bph;
        *(uint4*)&sm[BS_IDX(0, 1, brow, bu)] = *(const uint4*)Bpm;
        *(uint4*)&sm[BS_IDX(0, 2, brow, bu)] = *(const uint4*)Bpl;
    }
    __syncthreads();

    float a_stage[16];
    uint4 b_stage[3];

    for (int c = 0; c < NCHUNK; c++) {
        const int cur = c & 1, nxt = cur ^ 1;
        const bool has_next = (c + 1 < NCHUNK);
        if (has_next) {
            const int kn = (c + 1) * BK;
            const float4* ap4 = (const float4*)(Ap + kn);
#pragma unroll
            for (int j = 0; j < 4; j++) ((float4*)a_stage)[j] = ap4[j];
            b_stage[0] = *(const uint4*)(Bph + kn);
            b_stage[1] = *(const uint4*)(Bpm + kn);
            b_stage[2] = *(const uint4*)(Bpl + kn);
        }

        // ---- compute: 2 k16 steps from stage `cur` ----
#pragma unroll
        for (int ks = 0; ks < 2; ks++) {
            const int kb = ks * 16;
            uint32_t Bh_[4][2], Bm_[4][2], Bl_[4][2];
#pragma unroll
            for (int nt = 0; nt < 4; nt++) {
                const int n = wn + nt * 8 + g;
                Bh_[nt][0] = *(const uint32_t*)&sm[BS_IDX(cur, 0, n, kb + 2 * t)];
                Bh_[nt][1] = *(const uint32_t*)&sm[BS_IDX(cur, 0, n, kb + 2 * t + 8)];
                Bm_[nt][0] = *(const uint32_t*)&sm[BS_IDX(cur, 1, n, kb + 2 * t)];
                Bm_[nt][1] = *(const uint32_t*)&sm[BS_IDX(cur, 1, n, kb + 2 * t + 8)];
                Bl_[nt][0] = *(const uint32_t*)&sm[BS_IDX(cur, 2, n, kb + 2 * t)];
                Bl_[nt][1] = *(const uint32_t*)&sm[BS_IDX(cur, 2, n, kb + 2 * t + 8)];
            }
#pragma unroll
            for (int mt = 0; mt < 2; mt++) {
                const int r = wm + mt * 16 + g;
                uint32_t Ah[4], Am[4], Al[4];
                Ah[0] = *(const uint32_t*)&sm[AS_IDX(cur, 0, r, kb + 2 * t)];
                Ah[1] = *(const uint32_t*)&sm[AS_IDX(cur, 0, r + 8, kb + 2 * t)];
                Ah[2] = *(const uint32_t*)&sm[AS_IDX(cur, 0, r, kb + 2 * t + 8)];
                Ah[3] = *(const uint32_t*)&sm[AS_IDX(cur, 0, r + 8, kb + 2 * t + 8)];
                Am[0] = *(const uint32_t*)&sm[AS_IDX(cur, 1, r, kb + 2 * t)];
                Am[1] = *(const uint32_t*)&sm[AS_IDX(cur, 1, r + 8, kb + 2 * t)];
                Am[2] = *(const uint32_t*)&sm[AS_IDX(cur, 1, r, kb + 2 * t + 8)];
                Am[3] = *(const uint32_t*)&sm[AS_IDX(cur, 1, r + 8, kb + 2 * t + 8)];
                Al[0] = *(const uint32_t*)&sm[AS_IDX(cur, 2, r, kb + 2 * t)];
                Al[1] = *(const uint32_t*)&sm[AS_IDX(cur, 2, r + 8, kb + 2 * t)];
                Al[2] = *(const uint32_t*)&sm[AS_IDX(cur, 2, r, kb + 2 * t + 8)];
                Al[3] = *(const uint32_t*)&sm[AS_IDX(cur, 2, r + 8, kb + 2 * t + 8)];
#pragma unroll
                for (int nt = 0; nt < 4; nt++) {
                    mma16816(acc0[mt][nt], Ah, Bh_[nt]);   // hh        (scale 1)
                    mma16816(acc1[mt][nt], Ah, Bm_[nt]);   // h*m'      (scale 2^-11)
                    mma16816(acc1[mt][nt], Am, Bh_[nt]);   // m'*h      (scale 2^-11)
                    mma16816(acc2[mt][nt], Am, Bm_[nt]);   // m'm'      (scale 2^-22)
                    mma16816(acc2[mt][nt], Ah, Bl_[nt]);   // h*l'      (scale 2^-22)
                    mma16816(acc2[mt][nt], Al, Bh_[nt]);   // l'*h      (scale 2^-22)
                }
            }
        }

        // ---- stage next chunk into other buffer ----
        if (has_next) {
#pragma unroll
            for (int j = 0; j < 4; j++) {
                float4 v = ((float4*)a_stage)[j];
                uint32_t h0, m0_, l0, h1, m1_, l1;
                split3_2(v.x, v.y, h0, m0_, l0);
                split3_2(v.z, v.w, h1, m1_, l1);
                *(uint2*)&sm[AS_IDX(nxt, 0, arow, akoff + 4 * j)] = make_uint2(h0, h1);
                *(uint2*)&sm[AS_IDX(nxt, 1, arow, akoff + 4 * j)] = make_uint2(m0_, m1_);
                *(uint2*)&sm[AS_IDX(nxt, 2, arow, akoff + 4 * j)] = make_uint2(l0, l1);
            }
            *(uint4*)&sm[BS_IDX(nxt, 0, brow, bu)] = b_stage[0];
            *(uint4*)&sm[BS_IDX(nxt, 1, brow, bu)] = b_stage[1];
            *(uint4*)&sm[BS_IDX(nxt, 2, brow, bu)] = b_stage[2];
        }
        __syncthreads();
    }

    // ---- epilogue: recombine scales, sigmoid, store ----
#pragma unroll
    for (int mt = 0; mt < 2; mt++) {
        const int r0 = m0 + wm + mt * 16 + g;
#pragma unroll
        for (int nt = 0; nt < 4; nt++) {
            const int cc = n0 + wn + nt * 8 + 2 * t;
            float z0 = acc0[mt][nt][0] + (acc1[mt][nt][0] + acc2[mt][nt][0] * SC_DN1) * SC_DN1;
            float z1 = acc0[mt][nt][1] + (acc1[mt][nt][1] + acc2[mt][nt][1] * SC_DN1) * SC_DN1;
            float z2 = acc0[mt][nt][2] + (acc1[mt][nt][2] + acc2[mt][nt][2] * SC_DN1) * SC_DN1;
            float z3 = acc0[mt][nt][3] + (acc1[mt][nt][3] + acc2[mt][nt][3] * SC_DN1) * SC_DN1;
            float2 v0, v1;
            v0.x = 1.0f / (1.0f + expf(-z0));
            v0.y = 1.0f / (1.0f + expf(-z1));
            v1.x = 1.0f / (1.0f + expf(-z2));
            v1.y = 1.0f / (1.0f + expf(-z3));
            *(float2*)(g_scores + (size_t)r0 * E_EXP + cc) = v0;
            *(float2*)(g_scores + (size_t)(r0 + 8) * E_EXP + cc) = v1;
        }
    }
#undef AS_IDX
#undef BS_IDX
}

// ---------------------------------------------------------------------------
// Routing: one block per token; warp == group. jax top_k tie semantics.
// ---------------------------------------------------------------------------
__global__ __launch_bounds__(256) void route_kernel(
    const float* __restrict__ bias, float* __restrict__ out, int write_indices) {
    const int tok = blockIdx.x;
    const int e = threadIdx.x;
    const int lane = e & 31;
    const int warp = e >> 5;

    __shared__ float gsc[N_GROUPS];
    __shared__ unsigned keepmask;
    __shared__ float wv[N_GROUPS];
    __shared__ int wi[N_GROUPS];
    __shared__ int sel_idx[TOP_K];
    __shared__ int sel_warp;
    __shared__ float selw[TOP_K];

    const float score = g_scores[(size_t)tok * E_EXP + e];
    const float s = score + bias[e];

    {
        float v = s; int i = lane;
#pragma unroll
        for (int off = 16; off; off >>= 1) {
            float ov = __shfl_xor_sync(0xffffffffu, v, off);
            int oi = __shfl_xor_sync(0xffffffffu, i, off);
            if (ov > v || (ov == v && oi < i)) { v = ov; i = oi; }
        }
        float m1 = v;
        float v2 = (lane == i) ? -FLT_MAX : s;
#pragma unroll
        for (int off = 16; off; off >>= 1) v2 = fmaxf(v2, __shfl_xor_sync(0xffffffffu, v2, off));
        if (lane == 0) gsc[warp] = m1 + v2;
    }
    __syncthreads();

    if (e == 0) {
        unsigned m = 0;
#pragma unroll
        for (int it = 0; it < TOPK_GROUPS; it++) {
            int best = -1; float bv = -FLT_MAX;
#pragma unroll
            for (int gg = 0; gg < N_GROUPS; gg++)
                if (!((m >> gg) & 1u) && gsc[gg] > bv) { bv = gsc[gg]; best = gg; }
            m |= (1u << best);
        }
        keepmask = m;
    }
    __syncthreads();

    float cur = ((keepmask >> warp) & 1u) ? s : 0.0f;

    auto warp_best = [&](float v) {
        int i = e;
#pragma unroll
        for (int off = 16; off; off >>= 1) {
            float ov = __shfl_xor_sync(0xffffffffu, v, off);
            int oi = __shfl_xor_sync(0xffffffffu, i, off);
            if (ov > v || (ov == v && oi < i)) { v = ov; i = oi; }
        }
        if (lane == 0) { wv[warp] = v; wi[warp] = i; }
    };

    warp_best(cur);
    __syncthreads();

    for (int k = 0; k < TOP_K; k++) {
        if (e == 0) {
            int b = 0;
#pragma unroll
            for (int gg = 1; gg < N_GROUPS; gg++)
                if (wv[gg] > wv[b] || (wv[gg] == wv[b] && wi[gg] < wi[b])) b = gg;
            sel_idx[k] = wi[b];
            sel_warp = b;
        }
        __syncthreads();
        int sw = sel_warp;
        if (warp == sw) {
            if (e == sel_idx[k]) cur = -FLT_MAX;
            warp_best(cur);
        }
        __syncthreads();
    }

    if (e < TOP_K) selw[e] = g_scores[(size_t)tok * E_EXP + sel_idx[e]];
    __syncthreads();
    if (e == 0) {
        float sum = 0.0f;
#pragma unroll
        for (int k = 0; k < TOP_K; k++) sum += selw[k];
        float scale = 2.5f / (sum + 1e-20f);
#pragma unroll
        for (int k = 0; k < TOP_K; k++) {
            out[(size_t)tok * TOP_K + k] = selw[k] * scale;
            if (write_indices)
                out[(size_t)T_TOK * TOP_K + (size_t)tok * TOP_K + k] = (float)sel_idx[k];
        }
    }
}

// ---------------------------------------------------------------------------
extern "C" void kernel_launch(void* const* d_in, const int* in_sizes, int n_in,
                              void* d_out, int out_size) {
    const float* x = (const float*)d_in[0];
    const float* W = (const float*)d_in[1];
    const float* bias = (const float*)d_in[2];
    float* out = (float*)d_out;

    cudaFuncSetAttribute(gemm_hmma3_kernel,
                         cudaFuncAttributeMaxDynamicSharedMemorySize, SMEM_BYTES);

    wsplit_kernel<<<dim3(D_DIM / 32, E_EXP / 32), dim3(32, 8)>>>(W);
    gemm_hmma3_kernel<<<dim3(E_EXP / BN, T_TOK / BM), 256, SMEM_BYTES>>>(x);

    int write_indices = (out_size >= 2 * T_TOK * TOP_K) ? 1 : 0;
    route_kernel<<<T_TOK, 256>>>(bias, out, write_indices);
}

// round 7
// speedup vs baseline: 1.2977x; 1.1713x over previous
#include <cuda_runtime.h>
#include <cuda_fp16.h>
#include <float.h>
#include <math.h>
#include <stdint.h>

// ---------------- problem constants ----------------
#define T_TOK 8192
#define D_DIM 7168
#define E_EXP 256
#define N_GROUPS 8
#define TOPK_GROUPS 4
#define TOP_K 8

// ---------------- GEMM tiling ----------------
#define BM 128
#define BN 64
#define BK 32
#define NCHUNK (D_DIM / BK)      // 224

// smem rows: 40 halves = 80 bytes (16B-aligned rows; ldmatrix conflict-free)
#define ROW_B 80
#define A_SP_BYTES (128 * ROW_B)                 // 10240
#define B_SP_BYTES (64 * ROW_B)                  // 5120
#define A_OFF(st, sp) (((st) * 3 + (sp)) * A_SP_BYTES)
#define B_BASE (2 * 3 * A_SP_BYTES)              // 61440
#define B_OFF(st, sp) (B_BASE + ((st) * 3 + (sp)) * B_SP_BYTES)
#define SMEM_BYTES (B_BASE + 2 * 3 * B_SP_BYTES) // 92160

// piece scales: v = vh + vm*2^-11 + vl*2^-22 (pieces stored in fp16-normal range)
#define SC_UP1   2048.0f           // 2^11
#define SC_DN1   4.8828125e-4f     // 2^-11
#define SC_UP2   4194304.0f        // 2^22

// ---------------- device scratch ----------------
__device__ float g_scores[(size_t)T_TOK * E_EXP];     // sigmoid scores [T][E]
__device__ __half g_Bh[(size_t)E_EXP * D_DIM];        // W^T piece hi   [E][D]
__device__ __half g_Bm[(size_t)E_EXP * D_DIM];        // W^T piece mid (x 2^11)
__device__ __half g_Bl[(size_t)E_EXP * D_DIM];        // W^T piece lo  (x 2^22)

// ---------------- PTX helpers ----------------
__device__ __forceinline__ uint32_t smem_u32(const void* p) {
    uint32_t a;
    asm("{ .reg .u64 t; cvta.to.shared.u64 t, %1; cvt.u32.u64 %0, t; }" : "=r"(a) : "l"(p));
    return a;
}
__device__ __forceinline__ void mma16816(float* c, const uint32_t* a, const uint32_t* b) {
    asm volatile(
        "mma.sync.aligned.m16n8k16.row.col.f32.f16.f16.f32 "
        "{%0,%1,%2,%3}, {%4,%5,%6,%7}, {%8,%9}, {%0,%1,%2,%3};"
        : "+f"(c[0]), "+f"(c[1]), "+f"(c[2]), "+f"(c[3])
        : "r"(a[0]), "r"(a[1]), "r"(a[2]), "r"(a[3]), "r"(b[0]), "r"(b[1]));
}
__device__ __forceinline__ void ldsm4(uint32_t& r0, uint32_t& r1, uint32_t& r2, uint32_t& r3,
                                      uint32_t addr) {
    asm volatile("ldmatrix.sync.aligned.m8n8.x4.shared.b16 {%0,%1,%2,%3}, [%4];"
                 : "=r"(r0), "=r"(r1), "=r"(r2), "=r"(r3) : "r"(addr));
}
__device__ __forceinline__ void cpasync16(uint32_t saddr, const void* g) {
    asm volatile("cp.async.cg.shared.global [%0], [%1], 16;" :: "r"(saddr), "l"(g));
}
#define CP_COMMIT() asm volatile("cp.async.commit_group;" ::: "memory")
#define CP_WAIT0()  asm volatile("cp.async.wait_group 0;" ::: "memory")

// 3-way split of two floats -> three packed fp16 pairs (elem0 in low 16 bits)
__device__ __forceinline__ void split3_2(float fx, float fy,
                                         uint32_t& h, uint32_t& m, uint32_t& l) {
    __half hx = __float2half_rn(fx), hy = __float2half_rn(fy);
    float rx = fx - __half2float(hx), ry = fy - __half2float(hy);
    __half mx = __float2half_rn(rx * SC_UP1), my = __float2half_rn(ry * SC_UP1);
    float sx = rx - __half2float(mx) * SC_DN1, sy = ry - __half2float(my) * SC_DN1;
    __half lx = __float2half_rn(sx * SC_UP2), ly = __float2half_rn(sy * SC_UP2);
    h = ((uint32_t)__half_as_ushort(hy) << 16) | (uint32_t)__half_as_ushort(hx);
    m = ((uint32_t)__half_as_ushort(my) << 16) | (uint32_t)__half_as_ushort(mx);
    l = ((uint32_t)__half_as_ushort(ly) << 16) | (uint32_t)__half_as_ushort(lx);
}

// ---------------------------------------------------------------------------
// W split + transpose: W[k][e] f32 -> g_Bh/g_Bm/g_Bl [e][k]
// ---------------------------------------------------------------------------
__global__ __launch_bounds__(256) void wsplit_kernel(const float* __restrict__ W) {
    __shared__ float tile[32][33];
    const int k0 = blockIdx.x * 32, e0 = blockIdx.y * 32;
    const int tx = threadIdx.x, ty = threadIdx.y;   // 32 x 8
#pragma unroll
    for (int i = 0; i < 4; i++)
        tile[ty + 8 * i][tx] = W[(size_t)(k0 + ty + 8 * i) * E_EXP + e0 + tx];
    __syncthreads();
#pragma unroll
    for (int i = 0; i < 4; i++) {
        const int e = e0 + ty + 8 * i;
        const int k = k0 + tx;
        float f = tile[tx][ty + 8 * i];
        __half h = __float2half_rn(f);
        float r1 = f - __half2float(h);
        __half m = __float2half_rn(r1 * SC_UP1);
        float r2 = r1 - __half2float(m) * SC_DN1;
        __half l = __float2half_rn(r2 * SC_UP2);
        size_t o = (size_t)e * D_DIM + k;
        g_Bh[o] = h;
        g_Bm[o] = m;
        g_Bl[o] = l;
    }
}

// ---------------------------------------------------------------------------
// GEMM: scores = sigmoid(x @ W), fp16x3-split mma.sync (6 terms, fp32-exact).
// Grid (4, 64) = 256 CTAs. CTA 128x64, 8 warps 4(M)x2(N), warp tile 32x32.
// ldmatrix fragments, cp.async B, term-outer MMA order.
// ---------------------------------------------------------------------------
__global__ __launch_bounds__(256, 1) void gemm_hmma3_kernel(const float* __restrict__ x) {
    extern __shared__ char smc[];
    const uint32_t sb = smem_u32(smc);

    const int tid = threadIdx.x;
    const int lane = tid & 31, wid = tid >> 5;
    const int m0 = blockIdx.y * BM;
    const int n0 = blockIdx.x * BN;
    const int wm = (wid & 3) * 32;     // warp M offset
    const int wn = (wid >> 2) * 32;    // warp N offset
    const int g = lane >> 2;
    const int t = lane & 3;

    // ldmatrix per-lane offsets (bytes)
    const uint32_t laneA = (uint32_t)((lane & 15) * ROW_B + (lane >> 4) * 16);
    const uint32_t laneB = (uint32_t)(((lane & 7) + ((lane >> 4) & 1) * 8) * ROW_B +
                                      ((lane >> 3) & 1) * 16);

    float acc0[2][4][4], acc1[2][4][4], acc2[2][4][4];
#pragma unroll
    for (int i = 0; i < 2; i++)
#pragma unroll
        for (int j = 0; j < 4; j++)
#pragma unroll
            for (int q = 0; q < 4; q++) {
                acc0[i][j][q] = 0.0f; acc1[i][j][q] = 0.0f; acc2[i][j][q] = 0.0f;
            }

    // ---- global load mappings ----
    const int arow = tid >> 1;                 // 0..127
    const int akoff = (tid & 1) * 16;          // 0 or 16 (floats)
    const float* Ap = x + (size_t)(m0 + arow) * D_DIM + akoff;
    const int brow = tid >> 2;                 // 0..63
    const int bq = (tid & 3) * 8;              // halves (16B unit)
    const __half* Bp[3] = {
        g_Bh + (size_t)(n0 + brow) * D_DIM + bq,
        g_Bm + (size_t)(n0 + brow) * D_DIM + bq,
        g_Bl + (size_t)(n0 + brow) * D_DIM + bq };
    const uint32_t bDst = (uint32_t)(brow * ROW_B + (tid & 3) * 16);
    const uint32_t aDst = (uint32_t)(arow * ROW_B + akoff * 2);

    // ---- helper lambdas ----
    auto stsA = [&](int st, const float* src) {
#pragma unroll
        for (int j = 0; j < 4; j++) {
            float4 v = ((const float4*)src)[j];
            uint32_t h0, mm0, l0, h1, mm1, l1;
            split3_2(v.x, v.y, h0, mm0, l0);
            split3_2(v.z, v.w, h1, mm1, l1);
            const uint32_t o = aDst + 8 * j;   // 4 halves per uint2 = 8 bytes
            *(uint2*)(smc + A_OFF(st, 0) + o) = make_uint2(h0, h1);
            *(uint2*)(smc + A_OFF(st, 1) + o) = make_uint2(mm0, mm1);
            *(uint2*)(smc + A_OFF(st, 2) + o) = make_uint2(l0, l1);
        }
    };

    // ---- prologue: chunk 0 into stage 0 ----
    {
#pragma unroll
        for (int sp = 0; sp < 3; sp++) cpasync16(sb + B_OFF(0, sp) + bDst, Bp[sp]);
        CP_COMMIT();
        float a0[16];
#pragma unroll
        for (int j = 0; j < 4; j++) ((float4*)a0)[j] = ((const float4*)Ap)[j];
        stsA(0, a0);
        CP_WAIT0();
    }
    __syncthreads();

    float a_stage[16];

    for (int c = 0; c < NCHUNK; c++) {
        const int cur = c & 1, nxt = cur ^ 1;
        const bool has_next = (c + 1 < NCHUNK);
        if (has_next) {
            const int kn = (c + 1) * BK;
#pragma unroll
            for (int sp = 0; sp < 3; sp++) cpasync16(sb + B_OFF(nxt, sp) + bDst, Bp[sp] + kn);
            CP_COMMIT();
            const float4* ap4 = (const float4*)(Ap + kn);
#pragma unroll
            for (int j = 0; j < 4; j++) ((float4*)a_stage)[j] = ap4[j];
        }

        // ---- compute: 2 k16 steps from stage `cur` ----
#pragma unroll
        for (int ks = 0; ks < 2; ks++) {
            const uint32_t ko = (uint32_t)(ks * 32);
            const uint32_t aBase = sb + (uint32_t)(wm * ROW_B) + ko + laneA;
            const uint32_t bBase = sb + (uint32_t)(wn * ROW_B) + ko + laneB;

            uint32_t Ah[2][4], Am[2][4], Al[2][4];
            uint32_t Bh[4][2], Bx[4][2];

            // hh
            ldsm4(Ah[0][0], Ah[0][1], Ah[0][2], Ah[0][3], aBase + A_OFF(cur, 0));
            ldsm4(Ah[1][0], Ah[1][1], Ah[1][2], Ah[1][3], aBase + A_OFF(cur, 0) + 16 * ROW_B);
            ldsm4(Bh[0][0], Bh[0][1], Bh[1][0], Bh[1][1], bBase + B_OFF(cur, 0));
            ldsm4(Bh[2][0], Bh[2][1], Bh[3][0], Bh[3][1], bBase + B_OFF(cur, 0) + 16 * ROW_B);
#pragma unroll
            for (int mt = 0; mt < 2; mt++)
#pragma unroll
                for (int nt = 0; nt < 4; nt++) mma16816(acc0[mt][nt], Ah[mt], Bh[nt]);

            // hm
            ldsm4(Bx[0][0], Bx[0][1], Bx[1][0], Bx[1][1], bBase + B_OFF(cur, 1));
            ldsm4(Bx[2][0], Bx[2][1], Bx[3][0], Bx[3][1], bBase + B_OFF(cur, 1) + 16 * ROW_B);
#pragma unroll
            for (int mt = 0; mt < 2; mt++)
#pragma unroll
                for (int nt = 0; nt < 4; nt++) mma16816(acc1[mt][nt], Ah[mt], Bx[nt]);

            // mh, mm
            ldsm4(Am[0][0], Am[0][1], Am[0][2], Am[0][3], aBase + A_OFF(cur, 1));
            ldsm4(Am[1][0], Am[1][1], Am[1][2], Am[1][3], aBase + A_OFF(cur, 1) + 16 * ROW_B);
#pragma unroll
            for (int mt = 0; mt < 2; mt++)
#pragma unroll
                for (int nt = 0; nt < 4; nt++) mma16816(acc1[mt][nt], Am[mt], Bh[nt]);
#pragma unroll
            for (int mt = 0; mt < 2; mt++)
#pragma unroll
                for (int nt = 0; nt < 4; nt++) mma16816(acc2[mt][nt], Am[mt], Bx[nt]);

            // lh
            ldsm4(Al[0][0], Al[0][1], Al[0][2], Al[0][3], aBase + A_OFF(cur, 2));
            ldsm4(Al[1][0], Al[1][1], Al[1][2], Al[1][3], aBase + A_OFF(cur, 2) + 16 * ROW_B);
#pragma unroll
            for (int mt = 0; mt < 2; mt++)
#pragma unroll
                for (int nt = 0; nt < 4; nt++) mma16816(acc2[mt][nt], Al[mt], Bh[nt]);

            // hl
            ldsm4(Bx[0][0], Bx[0][1], Bx[1][0], Bx[1][1], bBase + B_OFF(cur, 2));
            ldsm4(Bx[2][0], Bx[2][1], Bx[3][0], Bx[3][1], bBase + B_OFF(cur, 2) + 16 * ROW_B);
#pragma unroll
            for (int mt = 0; mt < 2; mt++)
#pragma unroll
                for (int nt = 0; nt < 4; nt++) mma16816(acc2[mt][nt], Ah[mt], Bx[nt]);
        }

        if (has_next) {
            stsA(nxt, a_stage);
            CP_WAIT0();
        }
        __syncthreads();
    }

    // ---- epilogue: recombine scales, sigmoid, store ----
#pragma unroll
    for (int mt = 0; mt < 2; mt++) {
        const int r0 = m0 + wm + mt * 16 + g;
#pragma unroll
        for (int nt = 0; nt < 4; nt++) {
            const int cc = n0 + wn + nt * 8 + 2 * t;
            float z0 = acc0[mt][nt][0] + (acc1[mt][nt][0] + acc2[mt][nt][0] * SC_DN1) * SC_DN1;
            float z1 = acc0[mt][nt][1] + (acc1[mt][nt][1] + acc2[mt][nt][1] * SC_DN1) * SC_DN1;
            float z2 = acc0[mt][nt][2] + (acc1[mt][nt][2] + acc2[mt][nt][2] * SC_DN1) * SC_DN1;
            float z3 = acc0[mt][nt][3] + (acc1[mt][nt][3] + acc2[mt][nt][3] * SC_DN1) * SC_DN1;
            float2 v0, v1;
            v0.x = 1.0f / (1.0f + expf(-z0));
            v0.y = 1.0f / (1.0f + expf(-z1));
            v1.x = 1.0f / (1.0f + expf(-z2));
            v1.y = 1.0f / (1.0f + expf(-z3));
            *(float2*)(g_scores + (size_t)r0 * E_EXP + cc) = v0;
            *(float2*)(g_scores + (size_t)(r0 + 8) * E_EXP + cc) = v1;
        }
    }
}

// ---------------------------------------------------------------------------
// Routing: one block per token; warp == group. jax top_k tie semantics.
// ---------------------------------------------------------------------------
__global__ __launch_bounds__(256) void route_kernel(
    const float* __restrict__ bias, float* __restrict__ out, int write_indices) {
    const int tok = blockIdx.x;
    const int e = threadIdx.x;
    const int lane = e & 31;
    const int warp = e >> 5;

    __shared__ float gsc[N_GROUPS];
    __shared__ unsigned keepmask;
    __shared__ float wv[N_GROUPS];
    __shared__ int wi[N_GROUPS];
    __shared__ int sel_idx[TOP_K];
    __shared__ int sel_warp;
    __shared__ float selw[TOP_K];

    const float score = g_scores[(size_t)tok * E_EXP + e];
    const float s = score + bias[e];

    {
        float v = s; int i = lane;
#pragma unroll
        for (int off = 16; off; off >>= 1) {
            float ov = __shfl_xor_sync(0xffffffffu, v, off);
            int oi = __shfl_xor_sync(0xffffffffu, i, off);
            if (ov > v || (ov == v && oi < i)) { v = ov; i = oi; }
        }
        float m1 = v;
        float v2 = (lane == i) ? -FLT_MAX : s;
#pragma unroll
        for (int off = 16; off; off >>= 1) v2 = fmaxf(v2, __shfl_xor_sync(0xffffffffu, v2, off));
        if (lane == 0) gsc[warp] = m1 + v2;
    }
    __syncthreads();

    if (e == 0) {
        unsigned m = 0;
#pragma unroll
        for (int it = 0; it < TOPK_GROUPS; it++) {
            int best = -1; float bv = -FLT_MAX;
#pragma unroll
            for (int gg = 0; gg < N_GROUPS; gg++)
                if (!((m >> gg) & 1u) && gsc[gg] > bv) { bv = gsc[gg]; best = gg; }
            m |= (1u << best);
        }
        keepmask = m;
    }
    __syncthreads();

    float cur = ((keepmask >> warp) & 1u) ? s : 0.0f;

    auto warp_best = [&](float v) {
        int i = e;
#pragma unroll
        for (int off = 16; off; off >>= 1) {
            float ov = __shfl_xor_sync(0xffffffffu, v, off);
            int oi = __shfl_xor_sync(0xffffffffu, i, off);
            if (ov > v || (ov == v && oi < i)) { v = ov; i = oi; }
        }
        if (lane == 0) { wv[warp] = v; wi[warp] = i; }
    };

    warp_best(cur);
    __syncthreads();

    for (int k = 0; k < TOP_K; k++) {
        if (e == 0) {
            int b = 0;
#pragma unroll
            for (int gg = 1; gg < N_GROUPS; gg++)
                if (wv[gg] > wv[b] || (wv[gg] == wv[b] && wi[gg] < wi[b])) b = gg;
            sel_idx[k] = wi[b];
            sel_warp = b;
        }
        __syncthreads();
        int sw = sel_warp;
        if (warp == sw) {
            if (e == sel_idx[k]) cur = -FLT_MAX;
            warp_best(cur);
        }
        __syncthreads();
    }

    if (e < TOP_K) selw[e] = g_scores[(size_t)tok * E_EXP + sel_idx[e]];
    __syncthreads();
    if (e == 0) {
        float sum = 0.0f;
#pragma unroll
        for (int k = 0; k < TOP_K; k++) sum += selw[k];
        float scale = 2.5f / (sum + 1e-20f);
#pragma unroll
        for (int k = 0; k < TOP_K; k++) {
            out[(size_t)tok * TOP_K + k] = selw[k] * scale;
            if (write_indices)
                out[(size_t)T_TOK * TOP_K + (size_t)tok * TOP_K + k] = (float)sel_idx[k];
        }
    }
}

// ---------------------------------------------------------------------------
extern "C" void kernel_launch(void* const* d_in, const int* in_sizes, int n_in,
                              void* d_out, int out_size) {
    const float* x = (const float*)d_in[0];
    const float* W = (const float*)d_in[1];
    const float* bias = (const float*)d_in[2];
    float* out = (float*)d_out;

    cudaFuncSetAttribute(gemm_hmma3_kernel,
                         cudaFuncAttributeMaxDynamicSharedMemorySize, SMEM_BYTES);

    wsplit_kernel<<<dim3(D_DIM / 32, E_EXP / 32), dim3(32, 8)>>>(W);
    gemm_hmma3_kernel<<<dim3(E_EXP / BN, T_TOK / BM), 256, SMEM_BYTES>>>(x);

    int write_indices = (out_size >= 2 * T_TOK * TOP_K) ? 1 : 0;
    route_kernel<<<T_TOK, 256>>>(bias, out, write_indices);
}

// round 8
// speedup vs baseline: 1.3743x; 1.0591x over previous
#include <cuda_runtime.h>
#include <cuda_fp16.h>
#include <float.h>
#include <math.h>
#include <stdint.h>

// ---------------- problem constants ----------------
#define T_TOK 8192
#define D_DIM 7168
#define E_EXP 256
#define N_GROUPS 8
#define TOPK_GROUPS 4
#define TOP_K 8

// ---------------- GEMM tiling ----------------
#define BM 128
#define BN 64
#define BK 32
#define NCHUNK (D_DIM / BK)      // 224
#define NTHREADS 512

// smem rows: 40 halves = 80 bytes (16B-aligned rows; ldmatrix conflict-free)
#define ROW_B 80
#define A_SP_BYTES (128 * ROW_B)                 // 10240
#define B_SP_BYTES (64 * ROW_B)                  // 5120
#define A_OFF(st, sp) (((st) * 3 + (sp)) * A_SP_BYTES)
#define B_BASE (2 * 3 * A_SP_BYTES)              // 61440
#define B_OFF(st, sp) (B_BASE + ((st) * 3 + (sp)) * B_SP_BYTES)
#define SMEM_BYTES (B_BASE + 2 * 3 * B_SP_BYTES) // 92160

// piece scales: v = vh + vm*2^-11 + vl*2^-22 (pieces stored in fp16-normal range)
#define SC_UP1   2048.0f           // 2^11
#define SC_DN1   4.8828125e-4f     // 2^-11
#define SC_UP2   4194304.0f        // 2^22

// ---------------- device scratch ----------------
__device__ float g_scores[(size_t)T_TOK * E_EXP];     // sigmoid scores [T][E]
__device__ __half g_Bh[(size_t)E_EXP * D_DIM];        // W^T piece hi   [E][D]
__device__ __half g_Bm[(size_t)E_EXP * D_DIM];        // W^T piece mid (x 2^11)
__device__ __half g_Bl[(size_t)E_EXP * D_DIM];        // W^T piece lo  (x 2^22)

// ---------------- PTX helpers ----------------
__device__ __forceinline__ uint32_t smem_u32(const void* p) {
    uint32_t a;
    asm("{ .reg .u64 t; cvta.to.shared.u64 t, %1; cvt.u32.u64 %0, t; }" : "=r"(a) : "l"(p));
    return a;
}
__device__ __forceinline__ void mma16816(float* c, const uint32_t* a, const uint32_t* b) {
    asm volatile(
        "mma.sync.aligned.m16n8k16.row.col.f32.f16.f16.f32 "
        "{%0,%1,%2,%3}, {%4,%5,%6,%7}, {%8,%9}, {%0,%1,%2,%3};"
        : "+f"(c[0]), "+f"(c[1]), "+f"(c[2]), "+f"(c[3])
        : "r"(a[0]), "r"(a[1]), "r"(a[2]), "r"(a[3]), "r"(b[0]), "r"(b[1]));
}
__device__ __forceinline__ void ldsm4(uint32_t& r0, uint32_t& r1, uint32_t& r2, uint32_t& r3,
                                      uint32_t addr) {
    asm volatile("ldmatrix.sync.aligned.m8n8.x4.shared.b16 {%0,%1,%2,%3}, [%4];"
                 : "=r"(r0), "=r"(r1), "=r"(r2), "=r"(r3) : "r"(addr));
}
__device__ __forceinline__ void cpasync16(uint32_t saddr, const void* g) {
    asm volatile("cp.async.cg.shared.global [%0], [%1], 16;" :: "r"(saddr), "l"(g));
}
#define CP_COMMIT() asm volatile("cp.async.commit_group;" ::: "memory")
#define CP_WAIT0()  asm volatile("cp.async.wait_group 0;" ::: "memory")

// 3-way split of two floats -> three packed fp16 pairs (elem0 in low 16 bits)
__device__ __forceinline__ void split3_2(float fx, float fy,
                                         uint32_t& h, uint32_t& m, uint32_t& l) {
    __half hx = __float2half_rn(fx), hy = __float2half_rn(fy);
    float rx = fx - __half2float(hx), ry = fy - __half2float(hy);
    __half mx = __float2half_rn(rx * SC_UP1), my = __float2half_rn(ry * SC_UP1);
    float sx = rx - __half2float(mx) * SC_DN1, sy = ry - __half2float(my) * SC_DN1;
    __half lx = __float2half_rn(sx * SC_UP2), ly = __float2half_rn(sy * SC_UP2);
    h = ((uint32_t)__half_as_ushort(hy) << 16) | (uint32_t)__half_as_ushort(hx);
    m = ((uint32_t)__half_as_ushort(my) << 16) | (uint32_t)__half_as_ushort(mx);
    l = ((uint32_t)__half_as_ushort(ly) << 16) | (uint32_t)__half_as_ushort(lx);
}

// ---------------------------------------------------------------------------
// W split + transpose: W[k][e] f32 -> g_Bh/g_Bm/g_Bl [e][k]
// ---------------------------------------------------------------------------
__global__ __launch_bounds__(256) void wsplit_kernel(const float* __restrict__ W) {
    __shared__ float tile[32][33];
    const int k0 = blockIdx.x * 32, e0 = blockIdx.y * 32;
    const int tx = threadIdx.x, ty = threadIdx.y;   // 32 x 8
#pragma unroll
    for (int i = 0; i < 4; i++)
        tile[ty + 8 * i][tx] = W[(size_t)(k0 + ty + 8 * i) * E_EXP + e0 + tx];
    __syncthreads();
#pragma unroll
    for (int i = 0; i < 4; i++) {
        const int e = e0 + ty + 8 * i;
        const int k = k0 + tx;
        float f = tile[tx][ty + 8 * i];
        __half h = __float2half_rn(f);
        float r1 = f - __half2float(h);
        __half m = __float2half_rn(r1 * SC_UP1);
        float r2 = r1 - __half2float(m) * SC_DN1;
        __half l = __float2half_rn(r2 * SC_UP2);
        size_t o = (size_t)e * D_DIM + k;
        g_Bh[o] = h;
        g_Bm[o] = m;
        g_Bl[o] = l;
    }
}

// ---------------------------------------------------------------------------
// GEMM: scores = sigmoid(x @ W), fp16x3-split mma.sync (6 terms, fp32-exact).
// Grid (4, 64) = 256 CTAs. CTA 128x64, 512 threads, 16 warps 4(M)x4(N),
// warp tile 32x16. 4 warps/SMSP for latency hiding.
// ---------------------------------------------------------------------------
__global__ __launch_bounds__(NTHREADS, 1) void gemm_hmma3_kernel(const float* __restrict__ x) {
    extern __shared__ char smc[];
    const uint32_t sb = smem_u32(smc);

    const int tid = threadIdx.x;
    const int lane = tid & 31, wid = tid >> 5;
    const int m0 = blockIdx.y * BM;
    const int n0 = blockIdx.x * BN;
    const int wm = (wid & 3) * 32;     // warp M offset (4 warps down M)
    const int wn = (wid >> 2) * 16;    // warp N offset (4 warps across N)
    const int g = lane >> 2;
    const int t = lane & 3;

    // ldmatrix per-lane offsets (bytes)
    const uint32_t laneA = (uint32_t)((lane & 15) * ROW_B + (lane >> 4) * 16);
    const uint32_t laneB = (uint32_t)(((lane & 7) + ((lane >> 4) & 1) * 8) * ROW_B +
                                      ((lane >> 3) & 1) * 16);

    float acc0[2][2][4], acc1[2][2][4], acc2[2][2][4];
#pragma unroll
    for (int i = 0; i < 2; i++)
#pragma unroll
        for (int j = 0; j < 2; j++)
#pragma unroll
            for (int q = 0; q < 4; q++) {
                acc0[i][j][q] = 0.0f; acc1[i][j][q] = 0.0f; acc2[i][j][q] = 0.0f;
            }

    // ---- global load mappings ----
    // A: 512 threads, row = tid>>2 (0..127), 8 floats at akoff = (tid&3)*8
    const int arow = tid >> 2;
    const int akoff = (tid & 3) * 8;
    const float* Ap = x + (size_t)(m0 + arow) * D_DIM + akoff;
    const uint32_t aDst = (uint32_t)(arow * ROW_B + akoff * 2);
    // B: threads 0..255, row = tid>>2 (0..63), 16B unit at bq halves
    const int brow = tid >> 2;
    const int bq = (tid & 3) * 8;
    const __half* Bp[3] = {
        g_Bh + (size_t)(n0 + brow) * D_DIM + bq,
        g_Bm + (size_t)(n0 + brow) * D_DIM + bq,
        g_Bl + (size_t)(n0 + brow) * D_DIM + bq };
    const uint32_t bDst = (uint32_t)(brow * ROW_B + (tid & 3) * 16);
    const bool bLoader = (tid < 256);

    // ---- helper: split A registers (8 floats) to smem stage ----
    auto stsA = [&](int st, const float* src) {
#pragma unroll
        for (int j = 0; j < 2; j++) {
            float4 v = ((const float4*)src)[j];
            uint32_t h0, mm0, l0, h1, mm1, l1;
            split3_2(v.x, v.y, h0, mm0, l0);
            split3_2(v.z, v.w, h1, mm1, l1);
            const uint32_t o = aDst + 8 * j;
            *(uint2*)(smc + A_OFF(st, 0) + o) = make_uint2(h0, h1);
            *(uint2*)(smc + A_OFF(st, 1) + o) = make_uint2(mm0, mm1);
            *(uint2*)(smc + A_OFF(st, 2) + o) = make_uint2(l0, l1);
        }
    };

    // ---- prologue: chunk 0 into stage 0 ----
    {
        if (bLoader) {
#pragma unroll
            for (int sp = 0; sp < 3; sp++) cpasync16(sb + B_OFF(0, sp) + bDst, Bp[sp]);
        }
        CP_COMMIT();
        float a0[8];
#pragma unroll
        for (int j = 0; j < 2; j++) ((float4*)a0)[j] = ((const float4*)Ap)[j];
        stsA(0, a0);
        CP_WAIT0();
    }
    __syncthreads();

    float a_stage[8];

    for (int c = 0; c < NCHUNK; c++) {
        const int cur = c & 1, nxt = cur ^ 1;
        const bool has_next = (c + 1 < NCHUNK);
        if (has_next) {
            const int kn = (c + 1) * BK;
            if (bLoader) {
#pragma unroll
                for (int sp = 0; sp < 3; sp++) cpasync16(sb + B_OFF(nxt, sp) + bDst, Bp[sp] + kn);
            }
            CP_COMMIT();
            const float4* ap4 = (const float4*)(Ap + kn);
#pragma unroll
            for (int j = 0; j < 2; j++) ((float4*)a_stage)[j] = ap4[j];
        }

        // ---- compute: 2 k16 steps from stage `cur` ----
#pragma unroll
        for (int ks = 0; ks < 2; ks++) {
            const uint32_t ko = (uint32_t)(ks * 32);
            const uint32_t aBase = sb + (uint32_t)(wm * ROW_B) + ko + laneA;
            const uint32_t bBase = sb + (uint32_t)(wn * ROW_B) + ko + laneB;

            uint32_t Ah[2][4], Am[2][4], Al[2][4];
            uint32_t Bh[2][2], Bx[2][2];

            // hh
            ldsm4(Ah[0][0], Ah[0][1], Ah[0][2], Ah[0][3], aBase + A_OFF(cur, 0));
            ldsm4(Ah[1][0], Ah[1][1], Ah[1][2], Ah[1][3], aBase + A_OFF(cur, 0) + 16 * ROW_B);
            ldsm4(Bh[0][0], Bh[0][1], Bh[1][0], Bh[1][1], bBase + B_OFF(cur, 0));
#pragma unroll
            for (int mt = 0; mt < 2; mt++)
#pragma unroll
                for (int nt = 0; nt < 2; nt++) mma16816(acc0[mt][nt], Ah[mt], Bh[nt]);

            // hm
            ldsm4(Bx[0][0], Bx[0][1], Bx[1][0], Bx[1][1], bBase + B_OFF(cur, 1));
#pragma unroll
            for (int mt = 0; mt < 2; mt++)
#pragma unroll
                for (int nt = 0; nt < 2; nt++) mma16816(acc1[mt][nt], Ah[mt], Bx[nt]);

            // mh, mm
            ldsm4(Am[0][0], Am[0][1], Am[0][2], Am[0][3], aBase + A_OFF(cur, 1));
            ldsm4(Am[1][0], Am[1][1], Am[1][2], Am[1][3], aBase + A_OFF(cur, 1) + 16 * ROW_B);
#pragma unroll
            for (int mt = 0; mt < 2; mt++)
#pragma unroll
                for (int nt = 0; nt < 2; nt++) mma16816(acc1[mt][nt], Am[mt], Bh[nt]);
#pragma unroll
            for (int mt = 0; mt < 2; mt++)
#pragma unroll
                for (int nt = 0; nt < 2; nt++) mma16816(acc2[mt][nt], Am[mt], Bx[nt]);

            // lh
            ldsm4(Al[0][0], Al[0][1], Al[0][2], Al[0][3], aBase + A_OFF(cur, 2));
            ldsm4(Al[1][0], Al[1][1], Al[1][2], Al[1][3], aBase + A_OFF(cur, 2) + 16 * ROW_B);
#pragma unroll
            for (int mt = 0; mt < 2; mt++)
#pragma unroll
                for (int nt = 0; nt < 2; nt++) mma16816(acc2[mt][nt], Al[mt], Bh[nt]);

            // hl
            ldsm4(Bx[0][0], Bx[0][1], Bx[1][0], Bx[1][1], bBase + B_OFF(cur, 2));
#pragma unroll
            for (int mt = 0; mt < 2; mt++)
#pragma unroll
                for (int nt = 0; nt < 2; nt++) mma16816(acc2[mt][nt], Ah[mt], Bx[nt]);
        }

        if (has_next) {
            stsA(nxt, a_stage);
            CP_WAIT0();
        }
        __syncthreads();
    }

    // ---- epilogue: recombine scales, sigmoid, store ----
#pragma unroll
    for (int mt = 0; mt < 2; mt++) {
        const int r0 = m0 + wm + mt * 16 + g;
#pragma unroll
        for (int nt = 0; nt < 2; nt++) {
            const int cc = n0 + wn + nt * 8 + 2 * t;
            float z0 = acc0[mt][nt][0] + (acc1[mt][nt][0] + acc2[mt][nt][0] * SC_DN1) * SC_DN1;
            float z1 = acc0[mt][nt][1] + (acc1[mt][nt][1] + acc2[mt][nt][1] * SC_DN1) * SC_DN1;
            float z2 = acc0[mt][nt][2] + (acc1[mt][nt][2] + acc2[mt][nt][2] * SC_DN1) * SC_DN1;
            float z3 = acc0[mt][nt][3] + (acc1[mt][nt][3] + acc2[mt][nt][3] * SC_DN1) * SC_DN1;
            float2 v0, v1;
            v0.x = 1.0f / (1.0f + expf(-z0));
            v0.y = 1.0f / (1.0f + expf(-z1));
            v1.x = 1.0f / (1.0f + expf(-z2));
            v1.y = 1.0f / (1.0f + expf(-z3));
            *(float2*)(g_scores + (size_t)r0 * E_EXP + cc) = v0;
            *(float2*)(g_scores + (size_t)(r0 + 8) * E_EXP + cc) = v1;
        }
    }
}

// ---------------------------------------------------------------------------
// Routing: one block per token; warp == group. jax top_k tie semantics.
// ---------------------------------------------------------------------------
__global__ __launch_bounds__(256) void route_kernel(
    const float* __restrict__ bias, float* __restrict__ out, int write_indices) {
    const int tok = blockIdx.x;
    const int e = threadIdx.x;
    const int lane = e & 31;
    const int warp = e >> 5;

    __shared__ float gsc[N_GROUPS];
    __shared__ unsigned keepmask;
    __shared__ float wv[N_GROUPS];
    __shared__ int wi[N_GROUPS];
    __shared__ int sel_idx[TOP_K];
    __shared__ int sel_warp;
    __shared__ float selw[TOP_K];

    const float score = g_scores[(size_t)tok * E_EXP + e];
    const float s = score + bias[e];

    {
        float v = s; int i = lane;
#pragma unroll
        for (int off = 16; off; off >>= 1) {
            float ov = __shfl_xor_sync(0xffffffffu, v, off);
            int oi = __shfl_xor_sync(0xffffffffu, i, off);
            if (ov > v || (ov == v && oi < i)) { v = ov; i = oi; }
        }
        float m1 = v;
        float v2 = (lane == i) ? -FLT_MAX : s;
#pragma unroll
        for (int off = 16; off; off >>= 1) v2 = fmaxf(v2, __shfl_xor_sync(0xffffffffu, v2, off));
        if (lane == 0) gsc[warp] = m1 + v2;
    }
    __syncthreads();

    if (e == 0) {
        unsigned m = 0;
#pragma unroll
        for (int it = 0; it < TOPK_GROUPS; it++) {
            int best = -1; float bv = -FLT_MAX;
#pragma unroll
            for (int gg = 0; gg < N_GROUPS; gg++)
                if (!((m >> gg) & 1u) && gsc[gg] > bv) { bv = gsc[gg]; best = gg; }
            m |= (1u << best);
        }
        keepmask = m;
    }
    __syncthreads();

    float cur = ((keepmask >> warp) & 1u) ? s : 0.0f;

    auto warp_best = [&](float v) {
        int i = e;
#pragma unroll
        for (int off = 16; off; off >>= 1) {
            float ov = __shfl_xor_sync(0xffffffffu, v, off);
            int oi = __shfl_xor_sync(0xffffffffu, i, off);
            if (ov > v || (ov == v && oi < i)) { v = ov; i = oi; }
        }
        if (lane == 0) { wv[warp] = v; wi[warp] = i; }
    };

    warp_best(cur);
    __syncthreads();

    for (int k = 0; k < TOP_K; k++) {
        if (e == 0) {
            int b = 0;
#pragma unroll
            for (int gg = 1; gg < N_GROUPS; gg++)
                if (wv[gg] > wv[b] || (wv[gg] == wv[b] && wi[gg] < wi[b])) b = gg;
            sel_idx[k] = wi[b];
            sel_warp = b;
        }
        __syncthreads();
        int sw = sel_warp;
        if (warp == sw) {
            if (e == sel_idx[k]) cur = -FLT_MAX;
            warp_best(cur);
        }
        __syncthreads();
    }

    if (e < TOP_K) selw[e] = g_scores[(size_t)tok * E_EXP + sel_idx[e]];
    __syncthreads();
    if (e == 0) {
        float sum = 0.0f;
#pragma unroll
        for (int k = 0; k < TOP_K; k++) sum += selw[k];
        float scale = 2.5f / (sum + 1e-20f);
#pragma unroll
        for (int k = 0; k < TOP_K; k++) {
            out[(size_t)tok * TOP_K + k] = selw[k] * scale;
            if (write_indices)
                out[(size_t)T_TOK * TOP_K + (size_t)tok * TOP_K + k] = (float)sel_idx[k];
        }
    }
}

// ---------------------------------------------------------------------------
extern "C" void kernel_launch(void* const* d_in, const int* in_sizes, int n_in,
                              void* d_out, int out_size) {
    const float* x = (const float*)d_in[0];
    const float* W = (const float*)d_in[1];
    const float* bias = (const float*)d_in[2];
    float* out = (float*)d_out;

    cudaFuncSetAttribute(gemm_hmma3_kernel,
                         cudaFuncAttributeMaxDynamicSharedMemorySize, SMEM_BYTES);

    wsplit_kernel<<<dim3(D_DIM / 32, E_EXP / 32), dim3(32, 8)>>>(W);
    gemm_hmma3_kernel<<<dim3(E_EXP / BN, T_TOK / BM), NTHREADS, SMEM_BYTES>>>(x);

    int write_indices = (out_size >= 2 * T_TOK * TOP_K) ? 1 : 0;
    route_kernel<<<T_TOK, 256>>>(bias, out, write_indices);
}